// round 1
// baseline (speedup 1.0000x reference)
#include <cuda_runtime.h>
#include <cstdint>

// PairwiseDistance: out[b,i,j] = ||x[b,i]-y[b,j]||^2
//                 = ||x_i||^2 + ||y_j||^2 - 2 * <x_i, y_j>
// B=2, n=2048, d=64, fp32. Cross term via mma.sync tf32 tensor cores,
// norms kept in exact fp32.

#define BATCH 2
#define NROWS 2048
#define DDIM  64

#define BM 128
#define BN 128
#define KH 32        // K half (two phases cover DDIM=64)
#define SK 36        // smem row stride in floats (32 + 4 pad) -> conflict-free

__device__ float g_xnorm[BATCH * NROWS];
__device__ float g_ynorm[BATCH * NROWS];

// ---------------------------------------------------------------------------
// Row norms: one thread per row, exact fp32.
// ---------------------------------------------------------------------------
__global__ void norm_kernel(const float* __restrict__ x,
                            const float* __restrict__ y) {
    int idx = blockIdx.x * blockDim.x + threadIdx.x;   // 0 .. 2*BATCH*NROWS-1
    int which = idx >> 12;            // / (BATCH*NROWS) = /4096
    int r     = idx & 4095;
    const float* src = which ? y : x;
    const float4* p = (const float4*)(src + (size_t)r * DDIM);
    float s = 0.f;
#pragma unroll
    for (int i = 0; i < DDIM / 4; i++) {
        float4 v = p[i];
        s += v.x * v.x + v.y * v.y + v.z * v.z + v.w * v.w;
    }
    if (which) g_ynorm[r] = s;
    else       g_xnorm[r] = s;
}

// ---------------------------------------------------------------------------
// Main kernel: 128x128 output tile per block, 8 warps (2x4), each warp 64x32.
// mma.sync.aligned.m16n8k8.row.col.f32.tf32.tf32.f32
// ---------------------------------------------------------------------------
__global__ void __launch_bounds__(256, 2)
pdist_kernel(const float* __restrict__ x,
             const float* __restrict__ y,
             float* __restrict__ out) {
    __shared__ uint32_t xs[BM * SK];   // [m][k] row-major, tf32 bits
    __shared__ uint32_t ys[BN * SK];

    const int b  = blockIdx.z;
    const int i0 = blockIdx.y * BM;
    const int j0 = blockIdx.x * BN;
    const int tid = threadIdx.x;

    const float* xb = x + (size_t)b * NROWS * DDIM;
    const float* yb = y + (size_t)b * NROWS * DDIM;

    const int warp = tid >> 5;
    const int lane = tid & 31;
    const int wr = warp >> 2;          // 0..1  (64 rows each)
    const int wc = warp & 3;           // 0..3  (32 cols each)
    const int g   = lane >> 2;         // 0..7
    const int tig = lane & 3;          // 0..3

    float acc[4][4][4];
#pragma unroll
    for (int fm = 0; fm < 4; fm++)
#pragma unroll
        for (int fn = 0; fn < 4; fn++)
#pragma unroll
            for (int c = 0; c < 4; c++) acc[fm][fn][c] = 0.f;

#pragma unroll
    for (int kh = 0; kh < 2; kh++) {
        // ---- load K-half tiles, tf32-rounded, row-major stride SK ----
        // lanes read consecutive k -> coalesced; STS bank = k -> conflict-free
        for (int e = tid; e < BM * KH; e += 256) {
            int m = e >> 5;
            int k = e & 31;
            float vx = xb[(size_t)(i0 + m) * DDIM + kh * KH + k];
            float vy = yb[(size_t)(j0 + m) * DDIM + kh * KH + k];
            uint32_t tx, ty;
            asm("cvt.rna.tf32.f32 %0, %1;" : "=r"(tx) : "f"(vx));
            asm("cvt.rna.tf32.f32 %0, %1;" : "=r"(ty) : "f"(vy));
            xs[m * SK + k] = tx;
            ys[m * SK + k] = ty;
        }
        __syncthreads();

#pragma unroll
        for (int kk = 0; kk < KH; kk += 8) {
            uint32_t a[4][4], bb[4][2];
            // A fragments: a0=(g,tig) a1=(g+8,tig) a2=(g,tig+4) a3=(g+8,tig+4)
            // addr = (row)*SK + k ; bank = 4*g + tig -> 32 distinct lanes
#pragma unroll
            for (int fm = 0; fm < 4; fm++) {
                int mb = wr * 64 + fm * 16 + g;
                a[fm][0] = xs[(mb)     * SK + kk + tig];
                a[fm][1] = xs[(mb + 8) * SK + kk + tig];
                a[fm][2] = xs[(mb)     * SK + kk + tig + 4];
                a[fm][3] = xs[(mb + 8) * SK + kk + tig + 4];
            }
            // B fragments (col-major KxN): b0=(k=tig, n=g) b1=(k=tig+4, n=g)
#pragma unroll
            for (int fn = 0; fn < 4; fn++) {
                int nb = wc * 32 + fn * 8 + g;
                bb[fn][0] = ys[nb * SK + kk + tig];
                bb[fn][1] = ys[nb * SK + kk + tig + 4];
            }
#pragma unroll
            for (int fm = 0; fm < 4; fm++)
#pragma unroll
                for (int fn = 0; fn < 4; fn++)
                    asm volatile(
                        "mma.sync.aligned.m16n8k8.row.col.f32.tf32.tf32.f32 "
                        "{%0,%1,%2,%3}, {%4,%5,%6,%7}, {%8,%9}, {%0,%1,%2,%3};"
                        : "+f"(acc[fm][fn][0]), "+f"(acc[fm][fn][1]),
                          "+f"(acc[fm][fn][2]), "+f"(acc[fm][fn][3])
                        : "r"(a[fm][0]), "r"(a[fm][1]),
                          "r"(a[fm][2]), "r"(a[fm][3]),
                          "r"(bb[fn][0]), "r"(bb[fn][1]));
        }
        __syncthreads();
    }

    // ---- epilogue: out = xnorm + ynorm - 2*dot (norms exact fp32) ----
    float* outb = out + (size_t)b * NROWS * NROWS;
    const float* xn = g_xnorm + b * NROWS;
    const float* yn = g_ynorm + b * NROWS;

#pragma unroll
    for (int fm = 0; fm < 4; fm++) {
        int r0 = i0 + wr * 64 + fm * 16 + g;
        float xn0 = __ldg(xn + r0);
        float xn1 = __ldg(xn + r0 + 8);
#pragma unroll
        for (int fn = 0; fn < 4; fn++) {
            int c = j0 + wc * 32 + fn * 8 + 2 * tig;
            float yn0 = __ldg(yn + c);
            float yn1 = __ldg(yn + c + 1);
            float2 v0, v1;
            v0.x = xn0 + yn0 - 2.f * acc[fm][fn][0];
            v0.y = xn0 + yn1 - 2.f * acc[fm][fn][1];
            v1.x = xn1 + yn0 - 2.f * acc[fm][fn][2];
            v1.y = xn1 + yn1 - 2.f * acc[fm][fn][3];
            *(float2*)(outb + (size_t)r0 * NROWS + c)       = v0;
            *(float2*)(outb + (size_t)(r0 + 8) * NROWS + c) = v1;
        }
    }
}

// ---------------------------------------------------------------------------
extern "C" void kernel_launch(void* const* d_in, const int* in_sizes, int n_in,
                              void* d_out, int out_size) {
    const float* x = (const float*)d_in[0];
    const float* y = (const float*)d_in[1];
    float* out = (float*)d_out;

    norm_kernel<<<(2 * BATCH * NROWS) / 256, 256>>>(x, y);

    dim3 grid(NROWS / BN, NROWS / BM, BATCH);   // 16 x 16 x 2
    pdist_kernel<<<grid, 256>>>(x, y, out);
}

// round 5
// speedup vs baseline: 1.2336x; 1.2336x over previous
#include <cuda_runtime.h>
#include <cstdint>

// PairwiseDistance: out[b,i,j] = ||x_i||^2 + ||y_j||^2 - 2*<x_i,y_j>
// Cross term via mma.sync tf32 (tcgen05 unavailable: harness compiles at
// .target sm_103 without the 'a' feature). Norms exact fp32.
// B=2, n=2048, d=64.

#define BATCH 2
#define NROWS 2048
#define DDIM  64

#define BM 128
#define BN 128
#define SK 68        // smem row stride in floats (64 + 4 pad) -> conflict-free

#define SMEM_X 0
#define SMEM_Y (BM * SK * 4)
#define SMEM_TOTAL (2 * BM * SK * 4)   // 69632 B

__device__ float g_xnorm[BATCH * NROWS];
__device__ float g_ynorm[BATCH * NROWS];

// ---------------------------------------------------------------------------
// Row norms: one thread per row, exact fp32.
// ---------------------------------------------------------------------------
__global__ void norm_kernel(const float* __restrict__ x,
                            const float* __restrict__ y) {
    int idx = blockIdx.x * blockDim.x + threadIdx.x;
    int which = idx >> 12;
    int r     = idx & 4095;
    const float* src = which ? y : x;
    const float4* p = (const float4*)(src + (size_t)r * DDIM);
    float s = 0.f;
#pragma unroll
    for (int i = 0; i < DDIM / 4; i++) {
        float4 v = p[i];
        s += v.x * v.x + v.y * v.y + v.z * v.z + v.w * v.w;
    }
    if (which) g_ynorm[r] = s;
    else       g_xnorm[r] = s;
}

// ---------------------------------------------------------------------------
// Main kernel: 128x128 tile per CTA, 256 threads (8 warps, 2x4),
// warp tile 64x32. Full K=64 resident in smem; single barrier; the 8-kstep
// mma loop is barrier-free and fully unrolled so LDS pipelines under MMAs.
// ---------------------------------------------------------------------------
__global__ void __launch_bounds__(256, 2)
pdist_kernel(const float* __restrict__ x,
             const float* __restrict__ y,
             float* __restrict__ out) {
    extern __shared__ char smem[];
    uint32_t* xs = (uint32_t*)(smem + SMEM_X);
    uint32_t* ys = (uint32_t*)(smem + SMEM_Y);

    const int b  = blockIdx.z;
    const int i0 = blockIdx.y * BM;
    const int j0 = blockIdx.x * BN;
    const int tid = threadIdx.x;

    const float* xb = x + (size_t)b * NROWS * DDIM;
    const float* yb = y + (size_t)b * NROWS * DDIM;

    const int warp = tid >> 5;
    const int lane = tid & 31;
    const int wr = warp >> 2;          // 0..1  (64 rows each)
    const int wc = warp & 3;           // 0..3  (32 cols each)
    const int g   = lane >> 2;         // 0..7
    const int tig = lane & 3;          // 0..3

    // ---- load full 128x64 tiles, tf32-rounded; one barrier total ----
    // thread -> (row r, float4 chunk c); lanes cover consecutive k: coalesced.
#pragma unroll
    for (int i = 0; i < 8; i++) {
        int e = tid + i * 256;         // 0..2047 float4 chunks
        int r = e >> 4;
        int c = e & 15;
        float4 vx = *(const float4*)(xb + (size_t)(i0 + r) * DDIM + c * 4);
        float4 vy = *(const float4*)(yb + (size_t)(j0 + r) * DDIM + c * 4);
        uint4 tx, ty;
        asm("cvt.rna.tf32.f32 %0, %1;" : "=r"(tx.x) : "f"(vx.x));
        asm("cvt.rna.tf32.f32 %0, %1;" : "=r"(tx.y) : "f"(vx.y));
        asm("cvt.rna.tf32.f32 %0, %1;" : "=r"(tx.z) : "f"(vx.z));
        asm("cvt.rna.tf32.f32 %0, %1;" : "=r"(tx.w) : "f"(vx.w));
        asm("cvt.rna.tf32.f32 %0, %1;" : "=r"(ty.x) : "f"(vy.x));
        asm("cvt.rna.tf32.f32 %0, %1;" : "=r"(ty.y) : "f"(vy.y));
        asm("cvt.rna.tf32.f32 %0, %1;" : "=r"(ty.z) : "f"(vy.z));
        asm("cvt.rna.tf32.f32 %0, %1;" : "=r"(ty.w) : "f"(vy.w));
        *(uint4*)(xs + r * SK + c * 4) = tx;
        *(uint4*)(ys + r * SK + c * 4) = ty;
    }
    __syncthreads();

    float acc[4][4][4];
#pragma unroll
    for (int fm = 0; fm < 4; fm++)
#pragma unroll
        for (int fn = 0; fn < 4; fn++)
#pragma unroll
            for (int c = 0; c < 4; c++) acc[fm][fn][c] = 0.f;

    // ---- 8 k-steps, no barriers: ptxas pipelines LDS across MMAs ----
#pragma unroll
    for (int ks = 0; ks < 8; ks++) {
        const int kk = ks * 8;
        uint32_t a[4][4], bb[4][2];
#pragma unroll
        for (int fm = 0; fm < 4; fm++) {
            int mb = wr * 64 + fm * 16 + g;
            a[fm][0] = xs[(mb)     * SK + kk + tig];
            a[fm][1] = xs[(mb + 8) * SK + kk + tig];
            a[fm][2] = xs[(mb)     * SK + kk + tig + 4];
            a[fm][3] = xs[(mb + 8) * SK + kk + tig + 4];
        }
#pragma unroll
        for (int fn = 0; fn < 4; fn++) {
            int nb = wc * 32 + fn * 8 + g;
            bb[fn][0] = ys[nb * SK + kk + tig];
            bb[fn][1] = ys[nb * SK + kk + tig + 4];
        }
#pragma unroll
        for (int fm = 0; fm < 4; fm++)
#pragma unroll
            for (int fn = 0; fn < 4; fn++)
                asm volatile(
                    "mma.sync.aligned.m16n8k8.row.col.f32.tf32.tf32.f32 "
                    "{%0,%1,%2,%3}, {%4,%5,%6,%7}, {%8,%9}, {%0,%1,%2,%3};"
                    : "+f"(acc[fm][fn][0]), "+f"(acc[fm][fn][1]),
                      "+f"(acc[fm][fn][2]), "+f"(acc[fm][fn][3])
                    : "r"(a[fm][0]), "r"(a[fm][1]),
                      "r"(a[fm][2]), "r"(a[fm][3]),
                      "r"(bb[fn][0]), "r"(bb[fn][1]));
    }

    // ---- epilogue: out = xnorm + ynorm - 2*dot (norms exact fp32) ----
    float* outb = out + (size_t)b * NROWS * NROWS;
    const float* xn = g_xnorm + b * NROWS;
    const float* yn = g_ynorm + b * NROWS;

#pragma unroll
    for (int fm = 0; fm < 4; fm++) {
        int r0 = i0 + wr * 64 + fm * 16 + g;
        float xn0 = __ldg(xn + r0);
        float xn1 = __ldg(xn + r0 + 8);
#pragma unroll
        for (int fn = 0; fn < 4; fn++) {
            int c = j0 + wc * 32 + fn * 8 + 2 * tig;
            float yn0 = __ldg(yn + c);
            float yn1 = __ldg(yn + c + 1);
            float2 v0, v1;
            v0.x = xn0 + yn0 - 2.f * acc[fm][fn][0];
            v0.y = xn0 + yn1 - 2.f * acc[fm][fn][1];
            v1.x = xn1 + yn0 - 2.f * acc[fm][fn][2];
            v1.y = xn1 + yn1 - 2.f * acc[fm][fn][3];
            *(float2*)(outb + (size_t)r0 * NROWS + c)       = v0;
            *(float2*)(outb + (size_t)(r0 + 8) * NROWS + c) = v1;
        }
    }
}

// ---------------------------------------------------------------------------
extern "C" void kernel_launch(void* const* d_in, const int* in_sizes, int n_in,
                              void* d_out, int out_size) {
    const float* x = (const float*)d_in[0];
    const float* y = (const float*)d_in[1];
    float* out = (float*)d_out;

    cudaFuncSetAttribute(pdist_kernel,
                         cudaFuncAttributeMaxDynamicSharedMemorySize,
                         SMEM_TOTAL);

    norm_kernel<<<(2 * BATCH * NROWS) / 256, 256>>>(x, y);

    dim3 grid(NROWS / BN, NROWS / BM, BATCH);   // 16 x 16 x 2
    pdist_kernel<<<grid, 256, SMEM_TOTAL>>>(x, y, out);
}

// round 9
// speedup vs baseline: 1.3401x; 1.0863x over previous
#include <cuda_runtime.h>
#include <cstdint>

// PairwiseDistance: out[b,i,j] = ||x_i||^2 + ||y_j||^2 - 2*<x_i,y_j>
// Cross term via mma.sync tf32 (tcgen05 unavailable at harness .target sm_103).
// Norms exact fp32, computed in-kernel via shuffle reduction (no 2nd kernel).
// Smem tiles staged in FRAGMENT ORDER so the mainloop is 8 vector LDS +
// 16 MMA per warp-kstep.  B=2, n=2048, d=64.

#define BATCH 2
#define NROWS 2048
#define DDIM  64
#define BM 128
#define BN 128

// A perm: [wr(2)][fm(4)][ks(8)] slabs of 132 uint32 (128 data + 4 pad)
//   off = ((wr*4+fm)*8+ks)*132 + lane*4 + reg
// B perm: [wc(4)][fn(4)][ks(8)] slabs of 66 uint32 (64 data + 2 pad)
//   off = ((wc*4+fn)*8+ks)*66 + lane*2 + reg
#define A_WORDS (2 * 4 * 8 * 132)          // 8448
#define B_WORDS (4 * 4 * 8 * 66)           // 8448
#define SMEM_A 0
#define SMEM_B (A_WORDS * 4)               // 33792 B (16B aligned)
#define SMEM_XN (SMEM_B + B_WORDS * 4)     // 67584
#define SMEM_YN (SMEM_XN + 128 * 4)
#define SMEM_TOTAL (SMEM_YN + 128 * 4)     // 68608 B

__global__ void __launch_bounds__(256, 2)
pdist_kernel(const float* __restrict__ x,
             const float* __restrict__ y,
             float* __restrict__ out) {
    extern __shared__ char smem[];
    uint32_t* As = (uint32_t*)(smem + SMEM_A);
    uint32_t* Bs = (uint32_t*)(smem + SMEM_B);
    float* xn_s  = (float*)(smem + SMEM_XN);
    float* yn_s  = (float*)(smem + SMEM_YN);

    const int b  = blockIdx.z;
    const int i0 = blockIdx.y * BM;
    const int j0 = blockIdx.x * BN;
    const int tid = threadIdx.x;

    const float* xb = x + (size_t)b * NROWS * DDIM;
    const float* yb = y + (size_t)b * NROWS * DDIM;

    const int warp = tid >> 5;
    const int lane = tid & 31;
    const int wr = warp >> 2;          // 0..1
    const int wc = warp & 3;           // 0..3
    const int g   = lane >> 2;         // 0..7
    const int tig = lane & 3;          // 0..3

    // ---- load tiles, compute exact-fp32 norms, scatter tf32 to frag order ----
    // iteration i: thread -> row r = (tid>>4) + i*16, chunk c = tid&15
    // (k = 4c..4c+3). 16 consecutive tids cover one full row.
#pragma unroll
    for (int i = 0; i < 8; i++) {
        int e = tid + i * 256;
        int r = e >> 4;
        int c = e & 15;
        float4 vx = *(const float4*)(xb + (size_t)(i0 + r) * DDIM + c * 4);
        float4 vy = *(const float4*)(yb + (size_t)(j0 + r) * DDIM + c * 4);

        // exact norms: reduce over the 16 lanes sharing this row
        float sx = vx.x * vx.x + vx.y * vx.y + vx.z * vx.z + vx.w * vx.w;
        float sy = vy.x * vy.x + vy.y * vy.y + vy.z * vy.z + vy.w * vy.w;
#pragma unroll
        for (int m = 1; m < 16; m <<= 1) {
            sx += __shfl_xor_sync(0xFFFFFFFFu, sx, m);
            sy += __shfl_xor_sync(0xFFFFFFFFu, sy, m);
        }
        if (c == 0) { xn_s[r] = sx; yn_s[r] = sy; }

        // tf32 round
        uint32_t tx[4], ty[4];
        asm("cvt.rna.tf32.f32 %0, %1;" : "=r"(tx[0]) : "f"(vx.x));
        asm("cvt.rna.tf32.f32 %0, %1;" : "=r"(tx[1]) : "f"(vx.y));
        asm("cvt.rna.tf32.f32 %0, %1;" : "=r"(tx[2]) : "f"(vx.z));
        asm("cvt.rna.tf32.f32 %0, %1;" : "=r"(tx[3]) : "f"(vx.w));
        asm("cvt.rna.tf32.f32 %0, %1;" : "=r"(ty[0]) : "f"(vy.x));
        asm("cvt.rna.tf32.f32 %0, %1;" : "=r"(ty[1]) : "f"(vy.y));
        asm("cvt.rna.tf32.f32 %0, %1;" : "=r"(ty[2]) : "f"(vy.z));
        asm("cvt.rna.tf32.f32 %0, %1;" : "=r"(ty[3]) : "f"(vy.w));

        // scatter into fragment-order layouts
        int ks = c >> 1, khalf = c & 1;
        {   // A: row r -> wr_a, fm, g_a, half ; value k=4c+j -> lane g_a*4+j
            int wr_a = r >> 6, fm = (r >> 4) & 3, g_a = r & 7, half = (r >> 3) & 1;
            int base = (((wr_a * 4 + fm) * 8) + ks) * 132 + khalf * 2 + half;
#pragma unroll
            for (int j = 0; j < 4; j++)
                As[base + (g_a * 4 + j) * 4] = tx[j];
        }
        {   // B: row r -> wc_b, fn, g_b ; reg = khalf
            int wc_b = r >> 5, fn = (r >> 3) & 3, g_b = r & 7;
            int base = (((wc_b * 4 + fn) * 8) + ks) * 66 + khalf;
#pragma unroll
            for (int j = 0; j < 4; j++)
                Bs[base + (g_b * 4 + j) * 2] = ty[j];
        }
    }
    __syncthreads();

    float acc[4][4][4];
#pragma unroll
    for (int fm = 0; fm < 4; fm++)
#pragma unroll
        for (int fn = 0; fn < 4; fn++)
#pragma unroll
            for (int cc = 0; cc < 4; cc++) acc[fm][fn][cc] = 0.f;

    // ---- mainloop: per kstep 4 LDS.128 + 4 LDS.64 + 16 MMA, no barriers ----
#pragma unroll
    for (int ks = 0; ks < 8; ks++) {
        uint4 a[4];
        uint2 bb[4];
#pragma unroll
        for (int fm = 0; fm < 4; fm++)
            a[fm] = *(const uint4*)&As[(((wr * 4 + fm) * 8) + ks) * 132 + lane * 4];
#pragma unroll
        for (int fn = 0; fn < 4; fn++)
            bb[fn] = *(const uint2*)&Bs[(((wc * 4 + fn) * 8) + ks) * 66 + lane * 2];
#pragma unroll
        for (int fm = 0; fm < 4; fm++)
#pragma unroll
            for (int fn = 0; fn < 4; fn++)
                asm volatile(
                    "mma.sync.aligned.m16n8k8.row.col.f32.tf32.tf32.f32 "
                    "{%0,%1,%2,%3}, {%4,%5,%6,%7}, {%8,%9}, {%0,%1,%2,%3};"
                    : "+f"(acc[fm][fn][0]), "+f"(acc[fm][fn][1]),
                      "+f"(acc[fm][fn][2]), "+f"(acc[fm][fn][3])
                    : "r"(a[fm].x), "r"(a[fm].y), "r"(a[fm].z), "r"(a[fm].w),
                      "r"(bb[fn].x), "r"(bb[fn].y));
    }

    // ---- epilogue: out = xnorm + ynorm - 2*dot ----
    float* outb = out + (size_t)b * NROWS * NROWS;

#pragma unroll
    for (int fm = 0; fm < 4; fm++) {
        int rl = wr * 64 + fm * 16 + g;
        int r0 = i0 + rl;
        float xn0 = xn_s[rl];
        float xn1 = xn_s[rl + 8];
#pragma unroll
        for (int fn = 0; fn < 4; fn++) {
            int cl = wc * 32 + fn * 8 + 2 * tig;
            int c = j0 + cl;
            float yn0 = yn_s[cl];
            float yn1 = yn_s[cl + 1];
            float2 v0, v1;
            v0.x = xn0 + yn0 - 2.f * acc[fm][fn][0];
            v0.y = xn0 + yn1 - 2.f * acc[fm][fn][1];
            v1.x = xn1 + yn0 - 2.f * acc[fm][fn][2];
            v1.y = xn1 + yn1 - 2.f * acc[fm][fn][3];
            *(float2*)(outb + (size_t)r0 * NROWS + c)       = v0;
            *(float2*)(outb + (size_t)(r0 + 8) * NROWS + c) = v1;
        }
    }
}

// ---------------------------------------------------------------------------
extern "C" void kernel_launch(void* const* d_in, const int* in_sizes, int n_in,
                              void* d_out, int out_size) {
    const float* x = (const float*)d_in[0];
    const float* y = (const float*)d_in[1];
    float* out = (float*)d_out;

    cudaFuncSetAttribute(pdist_kernel,
                         cudaFuncAttributeMaxDynamicSharedMemorySize,
                         SMEM_TOTAL);

    dim3 grid(NROWS / BN, NROWS / BM, BATCH);   // 16 x 16 x 2
    pdist_kernel<<<grid, 256, SMEM_TOTAL>>>(x, y, out);
}